// round 5
// baseline (speedup 1.0000x reference)
#include <cuda_runtime.h>
#include <cuda_bf16.h>
#include <cstdint>

// Problem constants
#define BATCH 32
#define N_ROI 2000
#define N_GT  100
#define N_LAB 21
#define K_POS 64
#define ROWS_PER_B (N_ROI * N_LAB)            // 42000
#define DELTA_FLOATS (BATCH * ROWS_PER_B * 4) // 5,376,000
#define TOTAL_ROWS (BATCH * ROWS_PER_B)       // 1,344,000
#define RPB 64                                 // rois per block in iou kernel

// Scratch (device globals; no runtime allocation)
__device__ unsigned int g_merged[BATCH * N_ROI];
__device__ int          g_maxidx[BATCH * N_ROI];
__device__ int          g_label [BATCH * N_ROI];   // gt label if positive, else -1
__device__ float4       g_delta [BATCH * N_ROI];   // valid only when positive

// ---------------------------------------------------------------------------
// Kernel A: per-roi max IoU + first-argmax over 100 gt boxes.
// 4 threads per roi (25 gt each), each thread keeps TWO independent running
// maxima (low half / high half of its segment) to halve the dependent
// compare chain; exact first-argmax semantics are preserved at every merge
// (B beats A only on strict >; A always holds the smaller indices).
// ---------------------------------------------------------------------------
__global__ void __launch_bounds__(256) iou_kernel(const float4* __restrict__ roi,
                                                  const float4* __restrict__ gt)
{
    __shared__ float4 sg[N_GT];
    __shared__ float  sga[N_GT];
    const int b = blockIdx.y;
    const int t = threadIdx.x;

    if (t < N_GT) {
        const float4 g = gt[b * N_GT + t];
        sg[t]  = g;
        sga[t] = __fmul_rn(__fsub_rn(g.z, g.x), __fsub_rn(g.w, g.y));
    }
    __syncthreads();

    const int local = t >> 2;                 // 0..63 : roi within block
    const int seg   = t & 3;                  // 0..3  : gt segment
    const int n     = blockIdx.x * RPB + local;

    float aI = 0.0f, aU = 1.0f; int ai = 0;   // accumulator A: indices m0..m0+12
    float cI = 0.0f, cU = 1.0f; int ci = 0;   // accumulator B: indices m0+13..m0+24

    if (n < N_ROI) {
        const float4 q = roi[b * N_ROI + n];
        const float by1 = q.x, bx1 = q.y, by2 = q.z, bx2 = q.w;
        const float bb_area = __fmul_rn(__fsub_rn(by2, by1), __fsub_rn(bx2, bx1));
        const int m0 = seg * 25;
        ai = m0; ci = m0 + 13;
#pragma unroll
        for (int i = 0; i < 13; ++i) {
            {   // A half: m0 + i
                const int m = m0 + i;
                const float4 g = sg[m];
                const float xt = fmaxf(bx1, g.y);
                const float yt = fmaxf(by1, g.x);
                const float xb = fminf(bx2, g.w);
                const float yb = fminf(by2, g.z);
                const float iw = fmaxf(__fsub_rn(xb, xt), 0.0f);
                const float ih = __fsub_rn(yb, yt);          // may be negative
                const float inter = __fmul_rn(iw, ih);       // <=0 when no overlap
                const float uni = __fsub_rn(__fadd_rn(bb_area, sga[m]), inter);
                if (__fmul_rn(inter, aU) > __fmul_rn(aI, uni)) { aI = inter; aU = uni; ai = m; }
            }
            if (i < 12) {   // B half: m0 + 13 + i
                const int m = m0 + 13 + i;
                const float4 g = sg[m];
                const float xt = fmaxf(bx1, g.y);
                const float yt = fmaxf(by1, g.x);
                const float xb = fminf(bx2, g.w);
                const float yb = fminf(by2, g.z);
                const float iw = fmaxf(__fsub_rn(xb, xt), 0.0f);
                const float ih = __fsub_rn(yb, yt);
                const float inter = __fmul_rn(iw, ih);
                const float uni = __fsub_rn(__fadd_rn(bb_area, sga[m]), inter);
                if (__fmul_rn(inter, cU) > __fmul_rn(cI, uni)) { cI = inter; cU = uni; ci = m; }
            }
        }
    }

    // Merge B into A: strict > only (A has smaller indices -> stable first-max).
    if (__fmul_rn(cI, aU) > __fmul_rn(aI, cU)) { aI = cI; aU = cU; ai = ci; }

    // Reduce across the 4 lanes of this roi (lanes are consecutive in warp).
#pragma unroll
    for (int off = 1; off < 4; off <<= 1) {
        const float oI = __shfl_xor_sync(0xFFFFFFFFu, aI, off);
        const float oU = __shfl_xor_sync(0xFFFFFFFFu, aU, off);
        const int   oi = __shfl_xor_sync(0xFFFFFFFFu, ai, off);
        const float x = __fmul_rn(oI, aU);
        const float y = __fmul_rn(aI, oU);
        if (x > y || (x == y && oi < ai)) { aI = oI; aU = oU; ai = oi; }
    }

    if (seg == 0 && n < N_ROI) {
        const float best = (aI > 0.0f) ? __fdividef(aI, aU) : 0.0f;
        g_merged[b * N_ROI + n] = __float_as_uint(best);  // >=0 -> monotone bits
        g_maxidx[b * N_ROI + n] = ai;
    }
}

// ---------------------------------------------------------------------------
// Kernel B: per-batch top-64 selection (exact stable-sort semantics) and
// per-roi label/delta records. One block per batch, 1024 threads, 2 rois/thr.
// ---------------------------------------------------------------------------
__global__ void __launch_bounds__(1024) select_kernel(const float4* __restrict__ roi,
                                                      const float4* __restrict__ gt,
                                                      const int*    __restrict__ gtlab)
{
    __shared__ unsigned int hist[256];
    __shared__ unsigned int ssum[256];
    __shared__ unsigned int s_prefix, s_k;
    __shared__ int warp_sums[32];

    const int b = blockIdx.x;
    const int t = threadIdx.x;
    const int n0 = 2 * t, n1 = 2 * t + 1;
    const bool act = (n0 < N_ROI);
    const int lane = t & 31, wid = t >> 5;

    const unsigned int* gm = g_merged + b * N_ROI;
    unsigned v0 = 0u, v1 = 0u;
    if (act) { v0 = gm[n0]; v1 = gm[n1]; }
    if (t == 0) { s_prefix = 0u; s_k = K_POS; }
    __syncthreads();

    // 4-pass MSB radix select of the K_POS-th largest value (1-indexed).
#pragma unroll
    for (int pass = 0; pass < 4; ++pass) {
        const int shift = 24 - 8 * pass;
        if (t < 256) hist[t] = 0u;
        __syncthreads();
        const unsigned pfx = s_prefix;
        const unsigned kk0 = s_k;
        const unsigned hm = (pass == 0) ? 0u
                          : (0xFFFFFFFFu << ((shift + 8 > 31) ? 31 : shift + 8));
        // match-aggregated histogram (bin 0 is extremely hot: all zero-IoU rois)
#pragma unroll
        for (int s = 0; s < 2; ++s) {
            const unsigned v = (s == 0) ? v0 : v1;
            unsigned key = 0x100u;  // no-op key
            unsigned bin = 0u;
            if (act && (v & hm) == (pfx & hm)) { bin = (v >> shift) & 255u; key = bin; }
            const unsigned mmask = __match_any_sync(0xFFFFFFFFu, key);
            if (key != 0x100u) {
                const int leader = __ffs(mmask) - 1;
                if (lane == leader) atomicAdd(&hist[bin], (unsigned)__popc(mmask));
            }
        }
        __syncthreads();
        // single-warp suffix (descending cumulative) sum over 256 bins
        if (t < 32) {
            unsigned v[8];
            unsigned sum = 0u;
#pragma unroll
            for (int i = 0; i < 8; ++i) { v[i] = hist[t * 8 + i]; sum += v[i]; }
            unsigned suf = sum;
#pragma unroll
            for (int off = 1; off < 32; off <<= 1) {
                const unsigned x = __shfl_down_sync(0xFFFFFFFFu, suf, off);
                if (t + off < 32) suf += x;
            }
            unsigned acc = suf - sum;  // sum of lanes > t
#pragma unroll
            for (int i = 7; i >= 0; --i) { acc += v[i]; ssum[t * 8 + i] = acc; }
        }
        __syncthreads();
        if (t < 256) {
            const unsigned cum   = ssum[t];
            const unsigned above = (t < 255) ? ssum[t + 1] : 0u;
            if (cum >= kk0 && above < kk0) {   // unique winner bin
                s_prefix = pfx | ((unsigned)t << shift);
                s_k = kk0 - above;             // rank among ties at this value
            }
        }
        __syncthreads();
    }

    const unsigned T  = s_prefix;   // bits of the 64th-largest merged IoU
    const unsigned kk = s_k;        // number of tie slots (index-ascending)

    // Exclusive prefix count of ties (preserves original-index stable order)
    const int f0 = (act && v0 == T) ? 1 : 0;
    const int f1 = (act && v1 == T) ? 1 : 0;
    const int c  = f0 + f1;
    int inc = c;
#pragma unroll
    for (int off = 1; off < 32; off <<= 1) {
        const int x = __shfl_up_sync(0xFFFFFFFFu, inc, off);
        if (lane >= off) inc += x;
    }
    if (lane == 31) warp_sums[wid] = inc;
    __syncthreads();
    if (t < 32) {
        const int v = warp_sums[t];
        int iv = v;
#pragma unroll
        for (int off = 1; off < 32; off <<= 1) {
            const int x = __shfl_up_sync(0xFFFFFFFFu, iv, off);
            if (t >= off) iv += x;
        }
        warp_sums[t] = iv - v;  // exclusive
    }
    __syncthreads();
    const int excl = warp_sums[wid] + (inc - c);

    if (!act) return;

    const bool pos0 = (v0 > T) || (f0 && (unsigned)excl        < kk);
    const bool pos1 = (v1 > T) || (f1 && (unsigned)(excl + f0) < kk);

#pragma unroll
    for (int s = 0; s < 2; ++s) {
        const int n = (s == 0) ? n0 : n1;
        const bool pos = (s == 0) ? pos0 : pos1;
        const int gi = b * N_ROI + n;
        if (!pos) { g_label[gi] = -1; continue; }
        const int mi = g_maxidx[gi];
        const float4 q = roi[gi];
        const float4 g = gt[b * N_GT + mi];
        float bw = q.w - q.y;
        float bh = q.z - q.x;
        const float bcx = q.y + 0.5f * bw;
        const float bcy = q.x + 0.5f * bh;
        const float gw = g.w - g.y;
        const float gh = g.z - g.x;
        const float gcx = g.y + 0.5f * gw;
        const float gcy = g.x + 0.5f * gh;
        bw = (bw == 0.0f) ? 1e-3f : bw;
        bh = (bh == 0.0f) ? 1e-3f : bh;
        const float dx = (gw == 0.0f) ? 0.0f : (gcx - bcx) / bw;
        const float dy = (gh == 0.0f) ? 0.0f : (gcy - bcy) / bh;
        const float dw = (gw == 0.0f) ? 0.0f : logf(gw / bw);
        const float dh = (gh == 0.0f) ? 0.0f : logf(gh / bh);
        g_delta[gi] = make_float4(dy, dx, dh, dw);
        g_label[gi] = gtlab[b * N_GT + mi];
    }
}

// ---------------------------------------------------------------------------
// Kernel C: expand to outputs. grid.y = batch; one thread per (n, l) row:
// writes the float4 delta row and the one-hot label float. Store bandwidth.
// ---------------------------------------------------------------------------
__global__ void __launch_bounds__(256) write_kernel(float* __restrict__ out)
{
    const int r = blockIdx.x * 256 + threadIdx.x;
    if (r >= ROWS_PER_B) return;
    const int b = blockIdx.y;
    const int n = r / N_LAB;
    const int l = r - n * N_LAB;
    const int idx = b * ROWS_PER_B + r;

    const int lab = g_label[b * N_ROI + n];
    float4 dv = make_float4(0.f, 0.f, 0.f, 0.f);
    if (lab == l) dv = g_delta[b * N_ROI + n];
    reinterpret_cast<float4*>(out)[idx] = dv;

    const int e = (lab < 0) ? 0 : lab;
    out[DELTA_FLOATS + idx] = (l == e) ? 1.0f : 0.0f;
}

// ---------------------------------------------------------------------------
extern "C" void kernel_launch(void* const* d_in, const int* in_sizes, int n_in,
                              void* d_out, int out_size)
{
    const float4* roi   = (const float4*)d_in[0];
    const float4* gt    = (const float4*)d_in[1];
    const int*    gtlab = (const int*)d_in[2];
    float*        out   = (float*)d_out;

    dim3 gA((N_ROI + RPB - 1) / RPB, BATCH);
    iou_kernel<<<gA, 256>>>(roi, gt);
    select_kernel<<<BATCH, 1024>>>(roi, gt, gtlab);
    dim3 gC((ROWS_PER_B + 255) / 256, BATCH);
    write_kernel<<<gC, 256>>>(out);
}

// round 7
// speedup vs baseline: 1.0028x; 1.0028x over previous
#include <cuda_runtime.h>
#include <cuda_bf16.h>
#include <cstdint>

// Problem constants
#define BATCH 32
#define N_ROI 2000
#define N_GT  100
#define N_LAB 21
#define K_POS 64
#define ROWS_PER_B (N_ROI * N_LAB)            // 42000
#define DELTA_FLOATS (BATCH * ROWS_PER_B * 4) // 5,376,000
#define TOTAL_ROWS (BATCH * ROWS_PER_B)       // 1,344,000
#define RPB 128                                // rois per block in iou kernel

// Scratch (device globals; no runtime allocation)
__device__ unsigned int g_merged[BATCH * N_ROI];
__device__ int          g_maxidx[BATCH * N_ROI];
__device__ int          g_label [BATCH * N_ROI];   // gt label if positive, else -1
__device__ float4       g_delta [BATCH * N_ROI];   // valid only when positive

// ---------------------------------------------------------------------------
// Kernel A: per-roi max IoU + first-argmax over 100 gt boxes.
// Key algebra: IoU = inter/(S - inter) with S = bb_area + gt_area is a
// strictly increasing function of t = inter/S, so argmax_m IoU == argmax_m
// inter_m/S_m. S does not depend on inter, so the in-loop union subtraction
// disappears; comparison is cross-multiplied (S > 0 always).
// 4 threads per roi-pair (25 gt each), 2 rois per thread sharing the gt LDS.
// Zero-overlap ties stay exact: 0 > 0 false -> first index wins.
// ---------------------------------------------------------------------------
__global__ void __launch_bounds__(256) iou_kernel(const float4* __restrict__ roi,
                                                  const float4* __restrict__ gt)
{
    __shared__ float4 sg[N_GT];
    __shared__ float  sga[N_GT];
    const int b = blockIdx.y;
    const int t = threadIdx.x;

    if (t < N_GT) {
        const float4 g = gt[b * N_GT + t];
        sg[t]  = g;
        sga[t] = __fmul_rn(__fsub_rn(g.z, g.x), __fsub_rn(g.w, g.y));
    }
    __syncthreads();

    const int local = t >> 2;                 // 0..63
    const int seg   = t & 3;                  // 0..3 : gt segment
    const int base  = blockIdx.x * RPB;
    const int n0    = base + local;           // roi 0
    const int n1    = base + 64 + local;      // roi 1
    const bool a0   = (n0 < N_ROI);
    const bool a1   = (n1 < N_ROI);

    float by10 = 0.f, bx10 = 0.f, by20 = 0.f, bx20 = 0.f, bb0 = 0.f;
    float by11 = 0.f, bx11 = 0.f, by21 = 0.f, bx21 = 0.f, bb1 = 0.f;
    if (a0) {
        const float4 q = roi[b * N_ROI + n0];
        by10 = q.x; bx10 = q.y; by20 = q.z; bx20 = q.w;
        bb0 = __fmul_rn(__fsub_rn(by20, by10), __fsub_rn(bx20, bx10));
    }
    if (a1) {
        const float4 q = roi[b * N_ROI + n1];
        by11 = q.x; bx11 = q.y; by21 = q.z; bx21 = q.w;
        bb1 = __fmul_rn(__fsub_rn(by21, by11), __fsub_rn(bx21, bx11));
    }

    const int m0 = seg * 25;
    float aI0 = 0.0f, aS0 = 1.0f; int ai0 = m0;   // best inter / best S / index
    float aI1 = 0.0f, aS1 = 1.0f; int ai1 = m0;

#pragma unroll
    for (int i = 0; i < 25; ++i) {
        const int m = m0 + i;
        const float4 g = sg[m];
        const float ga = sga[m];
        {   // roi 0
            const float xt = fmaxf(bx10, g.y);
            const float yt = fmaxf(by10, g.x);
            const float xb = fminf(bx20, g.w);
            const float yb = fminf(by20, g.z);
            const float iw = fmaxf(__fsub_rn(xb, xt), 0.0f);
            const float ih = __fsub_rn(yb, yt);            // may be negative
            const float inter = __fmul_rn(iw, ih);          // <=0 when no overlap
            const float S = __fadd_rn(bb0, ga);             // > 0
            if (__fmul_rn(inter, aS0) > __fmul_rn(aI0, S)) { aI0 = inter; aS0 = S; ai0 = m; }
        }
        {   // roi 1
            const float xt = fmaxf(bx11, g.y);
            const float yt = fmaxf(by11, g.x);
            const float xb = fminf(bx21, g.w);
            const float yb = fminf(by21, g.z);
            const float iw = fmaxf(__fsub_rn(xb, xt), 0.0f);
            const float ih = __fsub_rn(yb, yt);
            const float inter = __fmul_rn(iw, ih);
            const float S = __fadd_rn(bb1, ga);
            if (__fmul_rn(inter, aS1) > __fmul_rn(aI1, S)) { aI1 = inter; aS1 = S; ai1 = m; }
        }
    }

    // Reduce across the 4 lanes of each roi (lanes are consecutive in warp).
#pragma unroll
    for (int off = 1; off < 4; off <<= 1) {
        const float oI0 = __shfl_xor_sync(0xFFFFFFFFu, aI0, off);
        const float oS0 = __shfl_xor_sync(0xFFFFFFFFu, aS0, off);
        const int   oi0 = __shfl_xor_sync(0xFFFFFFFFu, ai0, off);
        const float x0 = __fmul_rn(oI0, aS0);
        const float y0 = __fmul_rn(aI0, oS0);
        if (x0 > y0 || (x0 == y0 && oi0 < ai0)) { aI0 = oI0; aS0 = oS0; ai0 = oi0; }

        const float oI1 = __shfl_xor_sync(0xFFFFFFFFu, aI1, off);
        const float oS1 = __shfl_xor_sync(0xFFFFFFFFu, aS1, off);
        const int   oi1 = __shfl_xor_sync(0xFFFFFFFFu, ai1, off);
        const float x1 = __fmul_rn(oI1, aS1);
        const float y1 = __fmul_rn(aI1, oS1);
        if (x1 > y1 || (x1 == y1 && oi1 < ai1)) { aI1 = oI1; aS1 = oS1; ai1 = oi1; }
    }

    if (seg == 0) {
        if (a0) {
            const float best = (aI0 > 0.0f)
                ? __fdividef(aI0, __fsub_rn(aS0, aI0)) : 0.0f;
            g_merged[b * N_ROI + n0] = __float_as_uint(best);
            g_maxidx[b * N_ROI + n0] = ai0;
        }
        if (a1) {
            const float best = (aI1 > 0.0f)
                ? __fdividef(aI1, __fsub_rn(aS1, aI1)) : 0.0f;
            g_merged[b * N_ROI + n1] = __float_as_uint(best);
            g_maxidx[b * N_ROI + n1] = ai1;
        }
    }
}

// ---------------------------------------------------------------------------
// Kernel B: per-batch top-64 selection (exact stable-sort semantics) and
// per-roi label/delta records. One block per batch, 1024 threads, 2 rois/thr.
// ---------------------------------------------------------------------------
__global__ void __launch_bounds__(1024) select_kernel(const float4* __restrict__ roi,
                                                      const float4* __restrict__ gt,
                                                      const int*    __restrict__ gtlab)
{
    __shared__ unsigned int hist[256];
    __shared__ unsigned int ssum[256];
    __shared__ unsigned int s_prefix, s_k;
    __shared__ int warp_sums[32];

    const int b = blockIdx.x;
    const int t = threadIdx.x;
    const int n0 = 2 * t, n1 = 2 * t + 1;
    const bool act = (n0 < N_ROI);
    const int lane = t & 31, wid = t >> 5;

    const unsigned int* gm = g_merged + b * N_ROI;
    unsigned v0 = 0u, v1 = 0u;
    if (act) { v0 = gm[n0]; v1 = gm[n1]; }
    if (t == 0) { s_prefix = 0u; s_k = K_POS; }
    __syncthreads();

    // 4-pass MSB radix select of the K_POS-th largest value (1-indexed).
#pragma unroll
    for (int pass = 0; pass < 4; ++pass) {
        const int shift = 24 - 8 * pass;
        if (t < 256) hist[t] = 0u;
        __syncthreads();
        const unsigned pfx = s_prefix;
        const unsigned kk0 = s_k;
        const unsigned hm = (pass == 0) ? 0u
                          : (0xFFFFFFFFu << ((shift + 8 > 31) ? 31 : shift + 8));
        // match-aggregated histogram (bin 0 is extremely hot: all zero-IoU rois)
#pragma unroll
        for (int s = 0; s < 2; ++s) {
            const unsigned v = (s == 0) ? v0 : v1;
            unsigned key = 0x100u;  // no-op key
            unsigned bin = 0u;
            if (act && (v & hm) == (pfx & hm)) { bin = (v >> shift) & 255u; key = bin; }
            const unsigned mmask = __match_any_sync(0xFFFFFFFFu, key);
            if (key != 0x100u) {
                const int leader = __ffs(mmask) - 1;
                if (lane == leader) atomicAdd(&hist[bin], (unsigned)__popc(mmask));
            }
        }
        __syncthreads();
        // single-warp suffix (descending cumulative) sum over 256 bins
        if (t < 32) {
            unsigned v[8];
            unsigned sum = 0u;
#pragma unroll
            for (int i = 0; i < 8; ++i) { v[i] = hist[t * 8 + i]; sum += v[i]; }
            unsigned suf = sum;
#pragma unroll
            for (int off = 1; off < 32; off <<= 1) {
                const unsigned x = __shfl_down_sync(0xFFFFFFFFu, suf, off);
                if (t + off < 32) suf += x;
            }
            unsigned acc = suf - sum;  // sum of lanes > t
#pragma unroll
            for (int i = 7; i >= 0; --i) { acc += v[i]; ssum[t * 8 + i] = acc; }
        }
        __syncthreads();
        if (t < 256) {
            const unsigned cum   = ssum[t];
            const unsigned above = (t < 255) ? ssum[t + 1] : 0u;
            if (cum >= kk0 && above < kk0) {   // unique winner bin
                s_prefix = pfx | ((unsigned)t << shift);
                s_k = kk0 - above;             // rank among ties at this value
            }
        }
        __syncthreads();
    }

    const unsigned T  = s_prefix;   // bits of the 64th-largest merged IoU
    const unsigned kk = s_k;        // number of tie slots (index-ascending)

    // Exclusive prefix count of ties (preserves original-index stable order)
    const int f0 = (act && v0 == T) ? 1 : 0;
    const int f1 = (act && v1 == T) ? 1 : 0;
    const int c  = f0 + f1;
    int inc = c;
#pragma unroll
    for (int off = 1; off < 32; off <<= 1) {
        const int x = __shfl_up_sync(0xFFFFFFFFu, inc, off);
        if (lane >= off) inc += x;
    }
    if (lane == 31) warp_sums[wid] = inc;
    __syncthreads();
    if (t < 32) {
        const int v = warp_sums[t];
        int iv = v;
#pragma unroll
        for (int off = 1; off < 32; off <<= 1) {
            const int x = __shfl_up_sync(0xFFFFFFFFu, iv, off);
            if (t >= off) iv += x;
        }
        warp_sums[t] = iv - v;  // exclusive
    }
    __syncthreads();
    const int excl = warp_sums[wid] + (inc - c);

    if (!act) return;

    const bool pos0 = (v0 > T) || (f0 && (unsigned)excl        < kk);
    const bool pos1 = (v1 > T) || (f1 && (unsigned)(excl + f0) < kk);

#pragma unroll
    for (int s = 0; s < 2; ++s) {
        const int n = (s == 0) ? n0 : n1;
        const bool pos = (s == 0) ? pos0 : pos1;
        const int gi = b * N_ROI + n;
        if (!pos) { g_label[gi] = -1; continue; }
        const int mi = g_maxidx[gi];
        const float4 q = roi[gi];
        const float4 g = gt[b * N_GT + mi];
        float bw = q.w - q.y;
        float bh = q.z - q.x;
        const float bcx = q.y + 0.5f * bw;
        const float bcy = q.x + 0.5f * bh;
        const float gw = g.w - g.y;
        const float gh = g.z - g.x;
        const float gcx = g.y + 0.5f * gw;
        const float gcy = g.x + 0.5f * gh;
        bw = (bw == 0.0f) ? 1e-3f : bw;
        bh = (bh == 0.0f) ? 1e-3f : bh;
        const float dx = (gw == 0.0f) ? 0.0f : (gcx - bcx) / bw;
        const float dy = (gh == 0.0f) ? 0.0f : (gcy - bcy) / bh;
        const float dw = (gw == 0.0f) ? 0.0f : logf(gw / bw);
        const float dh = (gh == 0.0f) ? 0.0f : logf(gh / bh);
        g_delta[gi] = make_float4(dy, dx, dh, dw);
        g_label[gi] = gtlab[b * N_GT + mi];
    }
}

// ---------------------------------------------------------------------------
// Kernel C: expand to outputs. grid.y = batch; one thread per (n, l) row:
// writes the float4 delta row and the one-hot label float. Store bandwidth.
// ---------------------------------------------------------------------------
__global__ void __launch_bounds__(256) write_kernel(float* __restrict__ out)
{
    const int r = blockIdx.x * 256 + threadIdx.x;
    if (r >= ROWS_PER_B) return;
    const int b = blockIdx.y;
    const int n = r / N_LAB;
    const int l = r - n * N_LAB;
    const int idx = b * ROWS_PER_B + r;

    const int lab = g_label[b * N_ROI + n];
    float4 dv = make_float4(0.f, 0.f, 0.f, 0.f);
    if (lab == l) dv = g_delta[b * N_ROI + n];
    reinterpret_cast<float4*>(out)[idx] = dv;

    const int e = (lab < 0) ? 0 : lab;
    out[DELTA_FLOATS + idx] = (l == e) ? 1.0f : 0.0f;
}

// ---------------------------------------------------------------------------
extern "C" void kernel_launch(void* const* d_in, const int* in_sizes, int n_in,
                              void* d_out, int out_size)
{
    const float4* roi   = (const float4*)d_in[0];
    const float4* gt    = (const float4*)d_in[1];
    const int*    gtlab = (const int*)d_in[2];
    float*        out   = (float*)d_out;

    dim3 gA((N_ROI + RPB - 1) / RPB, BATCH);
    iou_kernel<<<gA, 256>>>(roi, gt);
    select_kernel<<<BATCH, 1024>>>(roi, gt, gtlab);
    dim3 gC((ROWS_PER_B + 255) / 256, BATCH);
    write_kernel<<<gC, 256>>>(out);
}